// round 6
// baseline (speedup 1.0000x reference)
#include <cuda_runtime.h>

#define B_ 8
#define M_ 2048
#define N_ 2048
#define R_ 32
#define SPLITK 2
#define KS (N_ / SPLITK)     // 1024 per split
#define KT 32                // k-tile
#define BMT 128              // output-row tile

#define L1C 10.24f
#define L2C 10.24f
#define EPSC 1e-16f

typedef unsigned long long ull;

// Scratch (device globals; no allocation allowed)
__device__ float g_ap[SPLITK * B_ * M_ * R_];   // split-K GEMM partials
__device__ float g_bp[16 * B_ * R_ * R_];       // split-K gram partials
__device__ float g_b[B_ * R_ * R_];             // reduced gram matrix

// ---- f32x2 helpers (Blackwell packed fp32 pipe: SASS FFMA2) ------------
__device__ __forceinline__ ull pk2(float a, float b) {
    ull r; asm("mov.b64 %0, {%1,%2};" : "=l"(r) : "f"(a), "f"(b)); return r;
}
__device__ __forceinline__ void unpk2(ull p, float& a, float& b) {
    asm("mov.b64 {%0,%1}, %2;" : "=f"(a), "=f"(b) : "l"(p));
}
__device__ __forceinline__ ull ffma2(ull a, ull b, ull c) {
    ull d; asm("fma.rn.f32x2 %0, %1, %2, %3;" : "=l"(d) : "l"(a), "l"(b), "l"(c)); return d;
}

// ---------------------------------------------------------------------------
// Gram partials: g_bp[p][b][r][s] = partial of vin^T vin over 128-row slice.
// grid (16, B_), 256 threads. Deterministic (no atomics).
// ---------------------------------------------------------------------------
#define GCHUNK 128
__global__ void gram_partial_kernel(const float* __restrict__ vin) {
    __shared__ float vs[GCHUNK][R_];
    int b = blockIdx.y;
    int p = blockIdx.x;
    int k0 = p * GCHUNK;
    int tid = threadIdx.x;

    const float4* src = (const float4*)(vin + ((size_t)b * N_ + k0) * R_);
    float4* dst = (float4*)&vs[0][0];
#pragma unroll
    for (int i = 0; i < 4; i++) dst[tid + 256 * i] = src[tid + 256 * i];
    __syncthreads();

    int r  = tid >> 3;
    int s4 = (tid & 7) * 4;
    float ax = 0.f, ay = 0.f, az = 0.f, aw = 0.f;
#pragma unroll 8
    for (int m = 0; m < GCHUNK; m++) {
        float vr = vs[m][r];
        float4 sv = *(const float4*)&vs[m][s4];
        ax += vr * sv.x; ay += vr * sv.y; az += vr * sv.z; aw += vr * sv.w;
    }
    float* o = g_bp + ((size_t)p * B_ + b) * (R_ * R_) + r * R_ + s4;
    o[0] = ax; o[1] = ay; o[2] = az; o[3] = aw;
}

__global__ void reduce_b_kernel() {
    int i = blockIdx.x * blockDim.x + threadIdx.x;
    if (i < B_ * R_ * R_) {
        float s = 0.f;
#pragma unroll
        for (int p = 0; p < 16; p++) s += g_bp[(size_t)p * (B_ * R_ * R_) + i];
        g_b[i] = s;
    }
}

// ---------------------------------------------------------------------------
// a = x @ v. x tile stored PRE-BROADCAST as {x,x} ull pairs -> hot loop has
// no broadcast packs: per k-step 1 LDS.128 + 2 packs + 4x(LDS.64 + 2 FFMA2)
// = 15 issue slots per 16 FMA-pipe cycles. grid (M_/128, SPLITK, B_), 256 thr.
// ---------------------------------------------------------------------------
__global__ void __launch_bounds__(256, 2)
gemm_xv_kernel(const float* __restrict__ x, const float* __restrict__ v) {
    __shared__ ull   xs2[BMT][KT + 1];   // {x,x} pairs, pad -> conflict-free LDS.64
    __shared__ float vs[KT][R_];

    int b   = blockIdx.z;
    int ks  = blockIdx.y;
    int m0  = blockIdx.x * BMT;
    int tid = threadIdx.x;
    int ty  = tid >> 3;          // 0..31 -> rows ty*4 .. +3
    int tx  = tid & 7;           // cols tx*4 .. +3

    const float* xb = x + (size_t)b * M_ * N_ + (size_t)ks * KS;
    const float* vb = v + (size_t)b * N_ * R_ + (size_t)ks * KS * R_;

    int srow = tid >> 3;         // staging row base (0..31), +32*i
    int skc  = tid & 7;          // staging k-chunk (float4 granules)

    ull acc[4][2];
#pragma unroll
    for (int i = 0; i < 4; i++) { acc[i][0] = 0ull; acc[i][1] = 0ull; }

    // prefetch tile 0 into registers
    float4 px[4], pv;
#pragma unroll
    for (int i = 0; i < 4; i++)
        px[i] = *(const float4*)(xb + (size_t)(m0 + srow + 32 * i) * N_ + skc * 4);
    pv = ((const float4*)vb)[tid];

    for (int t = 0; t < KS / KT; t++) {
        // stage regs -> smem (x written pre-broadcast as {x,x})
#pragma unroll
        for (int i = 0; i < 4; i++) {
            int row = srow + 32 * i;
            xs2[row][skc * 4 + 0] = pk2(px[i].x, px[i].x);
            xs2[row][skc * 4 + 1] = pk2(px[i].y, px[i].y);
            xs2[row][skc * 4 + 2] = pk2(px[i].z, px[i].z);
            xs2[row][skc * 4 + 3] = pk2(px[i].w, px[i].w);
        }
        ((float4*)&vs[0][0])[tid] = pv;
        __syncthreads();

        // prefetch next tile (overlaps compute)
        if (t + 1 < KS / KT) {
            int kb = (t + 1) * KT;
#pragma unroll
            for (int i = 0; i < 4; i++)
                px[i] = *(const float4*)(xb + (size_t)(m0 + srow + 32 * i) * N_ + kb + skc * 4);
            pv = ((const float4*)(vb + (size_t)kb * R_))[tid];
        }

#pragma unroll
        for (int k = 0; k < KT; k++) {
            float4 vf = *(const float4*)&vs[k][tx * 4];
            ull v01 = pk2(vf.x, vf.y);
            ull v23 = pk2(vf.z, vf.w);
#pragma unroll
            for (int i = 0; i < 4; i++) {
                ull xp = xs2[ty * 4 + i][k];
                acc[i][0] = ffma2(xp, v01, acc[i][0]);
                acc[i][1] = ffma2(xp, v23, acc[i][1]);
            }
        }
        __syncthreads();
    }

    float* ab = g_ap + ((size_t)(ks * B_ + b) * M_ + m0) * R_;
#pragma unroll
    for (int i = 0; i < 4; i++) {
        float4 o;
        unpk2(acc[i][0], o.x, o.y);
        unpk2(acc[i][1], o.z, o.w);
        *(float4*)(ab + (size_t)(ty * 4 + i) * R_ + tx * 4) = o;
    }
}

// ---------------------------------------------------------------------------
// a2 = x^T @ u. Pack along output-n (natural pairs from x tile).
// Per k-step: 2 LDS.128 + 2+4 packs + 8 FFMA2 = 16 issue / 16 FMA cycles.
// grid (N_/128, SPLITK, B_), 256 threads.
// ---------------------------------------------------------------------------
#define MT 32
__global__ void __launch_bounds__(256, 2)
gemm_xtu_kernel(const float* __restrict__ x, const float* __restrict__ u) {
    __shared__ float xs[MT][BMT];
    __shared__ float us[MT][R_];

    int b   = blockIdx.z;
    int ks  = blockIdx.y;
    int n0  = blockIdx.x * BMT;
    int tid = threadIdx.x;
    int ty  = tid >> 3;          // 0..31 -> n base ty*4 (2 output pairs)
    int tx  = tid & 7;           // cols tx*4 .. +3

    const float* xb = x + (size_t)b * M_ * N_ + (size_t)ks * KS * N_;
    const float* ub = u + (size_t)b * M_ * R_ + (size_t)ks * KS * R_;

    int smr = tid >> 5;          // staging m-row base (0..7), +8*i
    int snc = tid & 31;          // staging float4 column

    ull acc[2][4];
#pragma unroll
    for (int p = 0; p < 2; p++)
#pragma unroll
        for (int c = 0; c < 4; c++) acc[p][c] = 0ull;

    float4 px[4], pu;
#pragma unroll
    for (int i = 0; i < 4; i++)
        px[i] = *(const float4*)(xb + (size_t)(smr + 8 * i) * N_ + n0 + snc * 4);
    pu = ((const float4*)ub)[tid];

    for (int t = 0; t < KS / MT; t++) {
#pragma unroll
        for (int i = 0; i < 4; i++)
            *(float4*)&xs[smr + 8 * i][snc * 4] = px[i];
        ((float4*)&us[0][0])[tid] = pu;
        __syncthreads();

        if (t + 1 < KS / MT) {
            int mb = (t + 1) * MT;
#pragma unroll
            for (int i = 0; i < 4; i++)
                px[i] = *(const float4*)(xb + (size_t)(mb + smr + 8 * i) * N_ + n0 + snc * 4);
            pu = ((const float4*)(ub + (size_t)mb * R_))[tid];
        }

#pragma unroll
        for (int k = 0; k < MT; k++) {
            float4 xa = *(const float4*)&xs[k][ty * 4];
            ull xp0 = pk2(xa.x, xa.y);
            ull xp1 = pk2(xa.z, xa.w);
            float4 uf = *(const float4*)&us[k][tx * 4];
            ull u0 = pk2(uf.x, uf.x);
            ull u1 = pk2(uf.y, uf.y);
            ull u2 = pk2(uf.z, uf.z);
            ull u3 = pk2(uf.w, uf.w);
            acc[0][0] = ffma2(xp0, u0, acc[0][0]);
            acc[0][1] = ffma2(xp0, u1, acc[0][1]);
            acc[0][2] = ffma2(xp0, u2, acc[0][2]);
            acc[0][3] = ffma2(xp0, u3, acc[0][3]);
            acc[1][0] = ffma2(xp1, u0, acc[1][0]);
            acc[1][1] = ffma2(xp1, u1, acc[1][1]);
            acc[1][2] = ffma2(xp1, u2, acc[1][2]);
            acc[1][3] = ffma2(xp1, u3, acc[1][3]);
        }
        __syncthreads();
    }

    float* ab = g_ap + ((size_t)(ks * B_ + b) * N_ + n0) * R_;
#pragma unroll
    for (int p = 0; p < 2; p++) {
        float4 e, h;
        unpk2(acc[p][0], e.x, h.x);
        unpk2(acc[p][1], e.y, h.y);
        unpk2(acc[p][2], e.z, h.z);
        unpk2(acc[p][3], e.w, h.w);
        *(float4*)(ab + (size_t)(ty * 4 + 2 * p) * R_ + tx * 4)     = e;
        *(float4*)(ab + (size_t)(ty * 4 + 2 * p + 1) * R_ + tx * 4) = h;
    }
}

// ---------------------------------------------------------------------------
// Per-row Gauss-Seidel CD; sums the split-K partials of a on load.
// grid (M_/64, B_) = 256 blocks, 64 threads. One row per thread, in registers.
// ---------------------------------------------------------------------------
__global__ void cd_kernel(const float* __restrict__ uin, float* __restrict__ uout,
                          float l1, float l2) {
    __shared__ float bs[R_][R_];
    __shared__ float inv[R_];
    int b   = blockIdx.y;
    int tid = threadIdx.x;
    {
        const float4* src = (const float4*)(g_b + (size_t)b * R_ * R_);
        float4* dst = (float4*)&bs[0][0];
#pragma unroll
        for (int i = 0; i < 4; i++) dst[tid + 64 * i] = src[tid + 64 * i];
    }
    __syncthreads();
    if (tid < R_) inv[tid] = 1.0f / (bs[tid][tid] + l2 + EPSC);

    int m = blockIdx.x * 64 + tid;
    const float* a0 = g_ap + ((size_t)b * M_ + m) * R_;
    const float* a1 = a0 + (size_t)B_ * M_ * R_;
    const float* ur = uin + ((size_t)b * M_ + m) * R_;
    float areg[R_], ureg[R_];
#pragma unroll
    for (int i = 0; i < 8; i++) {
        float4 t0 = *(const float4*)(a0 + i * 4);
        float4 t1 = *(const float4*)(a1 + i * 4);
        areg[4*i+0] = t0.x + t1.x; areg[4*i+1] = t0.y + t1.y;
        areg[4*i+2] = t0.z + t1.z; areg[4*i+3] = t0.w + t1.w;
        float4 t2 = *(const float4*)(ur + i * 4);
        ureg[4*i+0] = t2.x; ureg[4*i+1] = t2.y; ureg[4*i+2] = t2.z; ureg[4*i+3] = t2.w;
    }
    __syncthreads();

#pragma unroll
    for (int r = 0; r < R_; r++) {
        float brr = bs[r][r];
        float d0 = 0.f, d1 = 0.f, d2 = 0.f, d3 = 0.f;
#pragma unroll
        for (int k = 0; k < R_; k += 4) {
            d0 += ureg[k + 0] * bs[k + 0][r];
            d1 += ureg[k + 1] * bs[k + 1][r];
            d2 += ureg[k + 2] * bs[k + 2][r];
            d3 += ureg[k + 3] * bs[k + 3][r];
        }
        float dot = (d0 + d1) + (d2 + d3);
        float z = areg[r] - (dot - ureg[r] * brr);
        float num = (z > l1) ? (z - l1) : ((z < -l1) ? (z + l1) : 0.0f);
        ureg[r] = (num + EPSC) * inv[r];
    }

    float* outr = uout + ((size_t)b * M_ + m) * R_;
#pragma unroll
    for (int i = 0; i < 8; i++) {
        float4 o = {ureg[4*i+0], ureg[4*i+1], ureg[4*i+2], ureg[4*i+3]};
        *(float4*)(outr + i * 4) = o;
    }
}

// ---------------------------------------------------------------------------
extern "C" void kernel_launch(void* const* d_in, const int* in_sizes, int n_in,
                              void* d_out, int out_size) {
    const float* x = (const float*)d_in[0];
    const float* u = (const float*)d_in[1];
    const float* v = (const float*)d_in[2];
    float* uout = (float*)d_out;                       // [B, M, R]
    float* vout = uout + (size_t)B_ * M_ * R_;         // [B, N, R]

    dim3 gg(16, B_);
    dim3 gm(M_ / BMT, SPLITK, B_);
    dim3 gn(N_ / BMT, SPLITK, B_);
    dim3 gc(M_ / 64, B_);

    // Phase 1: update u using original v
    gram_partial_kernel<<<gg, 256>>>(v);
    reduce_b_kernel<<<32, 256>>>();
    gemm_xv_kernel<<<gm, 256>>>(x, v);
    cd_kernel<<<gc, 64>>>(u, uout, L1C, L2C);

    // Phase 2: update v using NEW u
    gram_partial_kernel<<<gg, 256>>>(uout);
    reduce_b_kernel<<<32, 256>>>();
    gemm_xtu_kernel<<<gn, 256>>>(x, uout);
    cd_kernel<<<gc, 64>>>(v, vout, L1C, L2C);
}

// round 7
// speedup vs baseline: 1.2731x; 1.2731x over previous
#include <cuda_runtime.h>

#define B_ 8
#define M_ 2048
#define N_ 2048
#define R_ 32
#define SPLITK 4
#define KS (N_ / SPLITK)     // 512 per split
#define KT 32                // k-tile
#define BMT 256              // output-dim tile

#define L1C 10.24f
#define L2C 10.24f
#define EPSC 1e-16f

typedef unsigned long long ull;

// Scratch (device globals; no allocation allowed)
__device__ float g_ap[SPLITK * B_ * M_ * R_];   // split-K GEMM partials
__device__ float g_bp[16 * B_ * R_ * R_];       // split-K gram partials
__device__ float g_b[B_ * R_ * R_];             // reduced gram matrix

// ---- f32x2 helpers (Blackwell packed fp32 pipe: SASS FFMA2) ------------
__device__ __forceinline__ ull pk2(float a, float b) {
    ull r; asm("mov.b64 %0, {%1,%2};" : "=l"(r) : "f"(a), "f"(b)); return r;
}
__device__ __forceinline__ void unpk2(ull p, float& a, float& b) {
    asm("mov.b64 {%0,%1}, %2;" : "=f"(a), "=f"(b) : "l"(p));
}
__device__ __forceinline__ ull ffma2(ull a, ull b, ull c) {
    ull d; asm("fma.rn.f32x2 %0, %1, %2, %3;" : "=l"(d) : "l"(a), "l"(b), "l"(c)); return d;
}

// ---------------------------------------------------------------------------
// Gram partials: g_bp[p][b][r][s] over a 128-row slice. grid (16,B_), 256 thr.
// ---------------------------------------------------------------------------
#define GCHUNK 128
__global__ void gram_partial_kernel(const float* __restrict__ vin) {
    __shared__ float vs[GCHUNK][R_];
    int b = blockIdx.y;
    int p = blockIdx.x;
    int k0 = p * GCHUNK;
    int tid = threadIdx.x;

    const float4* src = (const float4*)(vin + ((size_t)b * N_ + k0) * R_);
    float4* dst = (float4*)&vs[0][0];
#pragma unroll
    for (int i = 0; i < 4; i++) dst[tid + 256 * i] = src[tid + 256 * i];
    __syncthreads();

    int r  = tid >> 3;
    int s4 = (tid & 7) * 4;
    float ax = 0.f, ay = 0.f, az = 0.f, aw = 0.f;
#pragma unroll 8
    for (int m = 0; m < GCHUNK; m++) {
        float vr = vs[m][r];
        float4 sv = *(const float4*)&vs[m][s4];
        ax += vr * sv.x; ay += vr * sv.y; az += vr * sv.z; aw += vr * sv.w;
    }
    float* o = g_bp + ((size_t)p * B_ + b) * (R_ * R_) + r * R_ + s4;
    o[0] = ax; o[1] = ay; o[2] = az; o[3] = aw;
}

__global__ void reduce_b_kernel() {
    int i = blockIdx.x * blockDim.x + threadIdx.x;
    if (i < B_ * R_ * R_) {
        float s = 0.f;
#pragma unroll
        for (int p = 0; p < 16; p++) s += g_bp[(size_t)p * (B_ * R_ * R_) + i];
        g_b[i] = s;
    }
}

// ---------------------------------------------------------------------------
// a = x @ v. Output-pair packing: acc[p][r] = {a[m2p][r], a[m2p+1][r]}.
// x tile stored reduce-major (transposed) xsT[k][m] -> x pairs via LDS.64.
// Per k-step: 1 LDS.128 + 4 MOV + 4 LDS.64 + 16 FFMA2 = 25 issue / 32 FMA cyc.
// grid (M_/256, SPLITK, B_), 256 threads, 2 CTAs/SM.
// ---------------------------------------------------------------------------
__global__ void __launch_bounds__(256, 2)
gemm_xv_kernel(const float* __restrict__ x, const float* __restrict__ v) {
    __shared__ float xsT[KT][BMT + 2];   // stride 258 (even: LDS.64-aligned, conflict-free reads)
    __shared__ float vs[KT][R_];

    int b   = blockIdx.z;
    int ks  = blockIdx.y;
    int m0  = blockIdx.x * BMT;
    int tid = threadIdx.x;
    int ty  = tid >> 3;          // 0..31 -> rows ty*8 .. +7 (4 pairs)
    int tx  = tid & 7;           // cols tx*4 .. +3

    const float* xb = x + (size_t)b * M_ * N_ + (size_t)ks * KS;
    const float* vb = v + (size_t)b * N_ * R_ + (size_t)ks * KS * R_;

    int srow = tid >> 3;         // staging row base (0..31), +32*i
    int skc  = tid & 7;          // staging k-chunk (float4 granules)

    ull acc[4][4];
#pragma unroll
    for (int p = 0; p < 4; p++)
#pragma unroll
        for (int c = 0; c < 4; c++) acc[p][c] = 0ull;

    // prefetch tile 0
    float4 px[8], pv;
#pragma unroll
    for (int i = 0; i < 8; i++)
        px[i] = *(const float4*)(xb + (size_t)(m0 + srow + 32 * i) * N_ + skc * 4);
    pv = ((const float4*)vb)[tid];

    for (int t = 0; t < KS / KT; t++) {
        // stage regs -> smem TRANSPOSED (k-major)
#pragma unroll
        for (int i = 0; i < 8; i++) {
            int row = srow + 32 * i;
            xsT[skc * 4 + 0][row] = px[i].x;
            xsT[skc * 4 + 1][row] = px[i].y;
            xsT[skc * 4 + 2][row] = px[i].z;
            xsT[skc * 4 + 3][row] = px[i].w;
        }
        ((float4*)&vs[0][0])[tid] = pv;
        __syncthreads();

        // prefetch next tile (overlaps compute)
        if (t + 1 < KS / KT) {
            int kb = (t + 1) * KT;
#pragma unroll
            for (int i = 0; i < 8; i++)
                px[i] = *(const float4*)(xb + (size_t)(m0 + srow + 32 * i) * N_ + kb + skc * 4);
            pv = ((const float4*)(vb + (size_t)kb * R_))[tid];
        }

#pragma unroll
        for (int k = 0; k < KT; k++) {
            float4 vf = *(const float4*)&vs[k][tx * 4];
            ull v0 = pk2(vf.x, vf.x);
            ull v1 = pk2(vf.y, vf.y);
            ull v2 = pk2(vf.z, vf.z);
            ull v3 = pk2(vf.w, vf.w);
#pragma unroll
            for (int p = 0; p < 4; p++) {
                ull xp = *(const ull*)&xsT[k][ty * 8 + 2 * p];
                acc[p][0] = ffma2(xp, v0, acc[p][0]);
                acc[p][1] = ffma2(xp, v1, acc[p][1]);
                acc[p][2] = ffma2(xp, v2, acc[p][2]);
                acc[p][3] = ffma2(xp, v3, acc[p][3]);
            }
        }
        __syncthreads();
    }

    float* ab = g_ap + ((size_t)(ks * B_ + b) * M_ + m0) * R_;
#pragma unroll
    for (int p = 0; p < 4; p++) {
        float4 e, h;
        unpk2(acc[p][0], e.x, h.x);
        unpk2(acc[p][1], e.y, h.y);
        unpk2(acc[p][2], e.z, h.z);
        unpk2(acc[p][3], e.w, h.w);
        *(float4*)(ab + (size_t)(ty * 8 + 2 * p) * R_ + tx * 4)     = e;
        *(float4*)(ab + (size_t)(ty * 8 + 2 * p + 1) * R_ + tx * 4) = h;
    }
}

// ---------------------------------------------------------------------------
// a2 = x^T @ u. Same inner loop; x tile is NATURALLY reduce-major (no transpose,
// STS.128 staging). grid (N_/256, SPLITK, B_), 256 threads, 2 CTAs/SM.
// ---------------------------------------------------------------------------
#define MT 32
__global__ void __launch_bounds__(256, 2)
gemm_xtu_kernel(const float* __restrict__ x, const float* __restrict__ u) {
    __shared__ float xs[MT][BMT];   // stride 256: reads conflict-free (pairs spread by 8 banks)
    __shared__ float us[MT][R_];

    int b   = blockIdx.z;
    int ks  = blockIdx.y;
    int n0  = blockIdx.x * BMT;
    int tid = threadIdx.x;
    int ty  = tid >> 3;          // 0..31 -> n ty*8 .. +7 (4 pairs)
    int tx  = tid & 7;

    const float* xb = x + (size_t)b * M_ * N_ + (size_t)ks * KS * N_;
    const float* ub = u + (size_t)b * M_ * R_ + (size_t)ks * KS * R_;

    int smr = tid >> 6;          // staging m-row base (0..3), +4*i
    int snc = tid & 63;          // staging float4 column

    ull acc[4][4];
#pragma unroll
    for (int p = 0; p < 4; p++)
#pragma unroll
        for (int c = 0; c < 4; c++) acc[p][c] = 0ull;

    float4 px[8], pu;
#pragma unroll
    for (int i = 0; i < 8; i++)
        px[i] = *(const float4*)(xb + (size_t)(smr + 4 * i) * N_ + n0 + snc * 4);
    pu = ((const float4*)ub)[tid];

    for (int t = 0; t < KS / MT; t++) {
#pragma unroll
        for (int i = 0; i < 8; i++)
            *(float4*)&xs[smr + 4 * i][snc * 4] = px[i];
        ((float4*)&us[0][0])[tid] = pu;
        __syncthreads();

        if (t + 1 < KS / MT) {
            int mb = (t + 1) * MT;
#pragma unroll
            for (int i = 0; i < 8; i++)
                px[i] = *(const float4*)(xb + (size_t)(mb + smr + 4 * i) * N_ + n0 + snc * 4);
            pu = ((const float4*)(ub + (size_t)mb * R_))[tid];
        }

#pragma unroll
        for (int k = 0; k < MT; k++) {
            float4 uf = *(const float4*)&us[k][tx * 4];
            ull u0 = pk2(uf.x, uf.x);
            ull u1 = pk2(uf.y, uf.y);
            ull u2 = pk2(uf.z, uf.z);
            ull u3 = pk2(uf.w, uf.w);
#pragma unroll
            for (int p = 0; p < 4; p++) {
                ull xp = *(const ull*)&xs[k][ty * 8 + 2 * p];
                acc[p][0] = ffma2(xp, u0, acc[p][0]);
                acc[p][1] = ffma2(xp, u1, acc[p][1]);
                acc[p][2] = ffma2(xp, u2, acc[p][2]);
                acc[p][3] = ffma2(xp, u3, acc[p][3]);
            }
        }
        __syncthreads();
    }

    float* ab = g_ap + ((size_t)(ks * B_ + b) * N_ + n0) * R_;
#pragma unroll
    for (int p = 0; p < 4; p++) {
        float4 e, h;
        unpk2(acc[p][0], e.x, h.x);
        unpk2(acc[p][1], e.y, h.y);
        unpk2(acc[p][2], e.z, h.z);
        unpk2(acc[p][3], e.w, h.w);
        *(float4*)(ab + (size_t)(ty * 8 + 2 * p) * R_ + tx * 4)     = e;
        *(float4*)(ab + (size_t)(ty * 8 + 2 * p + 1) * R_ + tx * 4) = h;
    }
}

// ---------------------------------------------------------------------------
// Per-row Gauss-Seidel CD; sums SPLITK partials of a on load.
// grid (M_/64, B_) = 256 blocks, 64 threads. One row per thread, in registers.
// ---------------------------------------------------------------------------
__global__ void cd_kernel(const float* __restrict__ uin, float* __restrict__ uout,
                          float l1, float l2) {
    __shared__ float bs[R_][R_];
    __shared__ float inv[R_];
    int b   = blockIdx.y;
    int tid = threadIdx.x;
    {
        const float4* src = (const float4*)(g_b + (size_t)b * R_ * R_);
        float4* dst = (float4*)&bs[0][0];
#pragma unroll
        for (int i = 0; i < 4; i++) dst[tid + 64 * i] = src[tid + 64 * i];
    }
    __syncthreads();
    if (tid < R_) inv[tid] = 1.0f / (bs[tid][tid] + l2 + EPSC);

    int m = blockIdx.x * 64 + tid;
    const size_t stride = (size_t)B_ * M_ * R_;
    const float* a0 = g_ap + ((size_t)b * M_ + m) * R_;
    const float* ur = uin + ((size_t)b * M_ + m) * R_;
    float areg[R_], ureg[R_];
#pragma unroll
    for (int i = 0; i < 8; i++) {
        float4 t0 = *(const float4*)(a0 + i * 4);
        float4 t1 = *(const float4*)(a0 + stride + i * 4);
        float4 t2 = *(const float4*)(a0 + 2 * stride + i * 4);
        float4 t3 = *(const float4*)(a0 + 3 * stride + i * 4);
        areg[4*i+0] = (t0.x + t1.x) + (t2.x + t3.x);
        areg[4*i+1] = (t0.y + t1.y) + (t2.y + t3.y);
        areg[4*i+2] = (t0.z + t1.z) + (t2.z + t3.z);
        areg[4*i+3] = (t0.w + t1.w) + (t2.w + t3.w);
        float4 tu = *(const float4*)(ur + i * 4);
        ureg[4*i+0] = tu.x; ureg[4*i+1] = tu.y; ureg[4*i+2] = tu.z; ureg[4*i+3] = tu.w;
    }
    __syncthreads();

#pragma unroll
    for (int r = 0; r < R_; r++) {
        float brr = bs[r][r];
        float d0 = 0.f, d1 = 0.f, d2 = 0.f, d3 = 0.f;
#pragma unroll
        for (int k = 0; k < R_; k += 4) {
            d0 += ureg[k + 0] * bs[k + 0][r];
            d1 += ureg[k + 1] * bs[k + 1][r];
            d2 += ureg[k + 2] * bs[k + 2][r];
            d3 += ureg[k + 3] * bs[k + 3][r];
        }
        float dot = (d0 + d1) + (d2 + d3);
        float z = areg[r] - (dot - ureg[r] * brr);
        float num = (z > l1) ? (z - l1) : ((z < -l1) ? (z + l1) : 0.0f);
        ureg[r] = (num + EPSC) * inv[r];
    }

    float* outr = uout + ((size_t)b * M_ + m) * R_;
#pragma unroll
    for (int i = 0; i < 8; i++) {
        float4 o = {ureg[4*i+0], ureg[4*i+1], ureg[4*i+2], ureg[4*i+3]};
        *(float4*)(outr + i * 4) = o;
    }
}

// ---------------------------------------------------------------------------
extern "C" void kernel_launch(void* const* d_in, const int* in_sizes, int n_in,
                              void* d_out, int out_size) {
    const float* x = (const float*)d_in[0];
    const float* u = (const float*)d_in[1];
    const float* v = (const float*)d_in[2];
    float* uout = (float*)d_out;                       // [B, M, R]
    float* vout = uout + (size_t)B_ * M_ * R_;         // [B, N, R]

    dim3 gg(16, B_);
    dim3 gm(M_ / BMT, SPLITK, B_);
    dim3 gn(N_ / BMT, SPLITK, B_);
    dim3 gc(M_ / 64, B_);

    // Phase 1: update u using original v
    gram_partial_kernel<<<gg, 256>>>(v);
    reduce_b_kernel<<<32, 256>>>();
    gemm_xv_kernel<<<gm, 256>>>(x, v);
    cd_kernel<<<gc, 64>>>(u, uout, L1C, L2C);

    // Phase 2: update v using NEW u
    gram_partial_kernel<<<gg, 256>>>(uout);
    reduce_b_kernel<<<32, 256>>>();
    gemm_xtu_kernel<<<gn, 256>>>(x, uout);
    cd_kernel<<<gc, 64>>>(v, vout, L1C, L2C);
}